// round 10
// baseline (speedup 1.0000x reference)
#include <cuda_runtime.h>
#include <cuda_bf16.h>
#include <math.h>
#include <cstdint>

#define D   64
#define NC  10
#define NS  4096
#define NCB 147              // mlp compute blocks (blockIdx 1..147)

__device__ __align__(16) float g_cc[NC * D];
__device__ int g_flag;

__device__ __forceinline__ void cp_async16(float* dst_smem, const float4* src) {
    unsigned int dst = (unsigned int)__cvta_generic_to_shared(dst_smem);
    asm volatile("cp.async.cg.shared.global [%0], [%1], 16;" :: "r"(dst), "l"(src));
}
__device__ __forceinline__ float fast_sigmoid(float x) { return 1.f / (1.f + __expf(-x)); }
__device__ __forceinline__ float fast_tanh(float x) {
    float e2 = __expf(2.f * x);
    return 1.f - 2.f / (e2 + 1.f);
}

// ---------------------------------------------------------------------------
// iter-role helpers (640 threads)
// ---------------------------------------------------------------------------
template<int R, int C>
__device__ __forceinline__ void stage_async(const float* __restrict__ W, float* s, int t) {
    const float4* g4 = (const float4*)W;
    constexpr int NF4 = R * C / 4;
    #pragma unroll
    for (int f = t; f < NF4; f += 640) {
        int r = (4 * f) / C;
        int c = (4 * f) % C;
        cp_async16(s + r * (C + 4) + c, g4 + f);
    }
}

// 5 clusters per thread, threads = ODIM*2
template<int ODIM, int INNER, int ACT>
__device__ __forceinline__ void mmr(const float* __restrict__ X,
                                    const float* __restrict__ sW,
                                    const float* __restrict__ B,
                                    float* __restrict__ out, int t) {
    constexpr int STR = INNER + 4;
    if (t < ODIM * 2) {
        int o  = t % ODIM;
        int n0 = (t / ODIM) * 5;
        const float* w  = sW + o * STR;
        const float* xb = X + n0 * INNER;
        float a0x=0.f,a0y=0.f,a1x=0.f,a1y=0.f,a2x=0.f,a2y=0.f,a3x=0.f,a3y=0.f,a4x=0.f,a4y=0.f;
        #pragma unroll
        for (int j = 0; j < INNER; j += 4) {
            float4 wv = *(const float4*)(w + j);
            float4 x0 = *(const float4*)(xb + j);
            float4 x1 = *(const float4*)(xb + INNER + j);
            float4 x2 = *(const float4*)(xb + 2 * INNER + j);
            float4 x3 = *(const float4*)(xb + 3 * INNER + j);
            float4 x4 = *(const float4*)(xb + 4 * INNER + j);
            a0x = fmaf(wv.x, x0.x, fmaf(wv.z, x0.z, a0x));
            a0y = fmaf(wv.y, x0.y, fmaf(wv.w, x0.w, a0y));
            a1x = fmaf(wv.x, x1.x, fmaf(wv.z, x1.z, a1x));
            a1y = fmaf(wv.y, x1.y, fmaf(wv.w, x1.w, a1y));
            a2x = fmaf(wv.x, x2.x, fmaf(wv.z, x2.z, a2x));
            a2y = fmaf(wv.y, x2.y, fmaf(wv.w, x2.w, a2y));
            a3x = fmaf(wv.x, x3.x, fmaf(wv.z, x3.z, a3x));
            a3y = fmaf(wv.y, x3.y, fmaf(wv.w, x3.w, a3y));
            a4x = fmaf(wv.x, x4.x, fmaf(wv.z, x4.z, a4x));
            a4y = fmaf(wv.y, x4.y, fmaf(wv.w, x4.w, a4y));
        }
        float bo = B[o];
        float r0 = a0x + a0y + bo, r1 = a1x + a1y + bo, r2 = a2x + a2y + bo;
        float r3 = a3x + a3y + bo, r4 = a4x + a4y + bo;
        if (ACT) {
            r0 = fmaxf(r0, 0.f); r1 = fmaxf(r1, 0.f); r2 = fmaxf(r2, 0.f);
            r3 = fmaxf(r3, 0.f); r4 = fmaxf(r4, 0.f);
        }
        out[(n0 + 0) * ODIM + o] = r0;
        out[(n0 + 1) * ODIM + o] = r1;
        out[(n0 + 2) * ODIM + o] = r2;
        out[(n0 + 3) * ODIM + o] = r3;
        out[(n0 + 4) * ODIM + o] = r4;
    }
}

// 2 clusters per thread, threads = ODIM*5 (wider occupancy for ODIM<=128)
template<int ODIM, int INNER, int ACT>
__device__ __forceinline__ void mmr2(const float* __restrict__ X,
                                     const float* __restrict__ sW,
                                     const float* __restrict__ B,
                                     float* __restrict__ out, int t) {
    constexpr int STR = INNER + 4;
    if (t < ODIM * 5) {
        int o  = t % ODIM;
        int n0 = (t / ODIM) * 2;
        const float* w  = sW + o * STR;
        const float* xb = X + n0 * INNER;
        float a0x=0.f,a0y=0.f,a1x=0.f,a1y=0.f;
        #pragma unroll
        for (int j = 0; j < INNER; j += 4) {
            float4 wv = *(const float4*)(w + j);
            float4 x0 = *(const float4*)(xb + j);
            float4 x1 = *(const float4*)(xb + INNER + j);
            a0x = fmaf(wv.x, x0.x, fmaf(wv.z, x0.z, a0x));
            a0y = fmaf(wv.y, x0.y, fmaf(wv.w, x0.w, a0y));
            a1x = fmaf(wv.x, x1.x, fmaf(wv.z, x1.z, a1x));
            a1y = fmaf(wv.y, x1.y, fmaf(wv.w, x1.w, a1y));
        }
        float bo = B[o];
        float r0 = a0x + a0y + bo, r1 = a1x + a1y + bo;
        if (ACT) { r0 = fmaxf(r0, 0.f); r1 = fmaxf(r1, 0.f); }
        out[(n0 + 0) * ODIM + o] = r0;
        out[(n0 + 1) * ODIM + o] = r1;
    }
}

__device__ __forceinline__ void lnw(const float* __restrict__ X,
                                    const float* __restrict__ gma,
                                    const float* __restrict__ bta,
                                    float* __restrict__ out,
                                    float* sred, int t) {
    if (t < 320) {
        int w = t >> 5, l = t & 31;
        float v0 = X[w * 64 + l], v1 = X[w * 64 + 32 + l];
        float s = v0 + v1, s2 = v0 * v0 + v1 * v1;
        #pragma unroll
        for (int off = 16; off; off >>= 1) {
            s  += __shfl_xor_sync(0xffffffffu, s, off);
            s2 += __shfl_xor_sync(0xffffffffu, s2, off);
        }
        if (l == 0) {
            float m = s * (1.f / 64.f);
            sred[w]      = m;
            sred[16 + w] = rsqrtf(s2 * (1.f / 64.f) - m * m + 1e-5f);
        }
    }
    __syncthreads();
    int n = t >> 6, ii = t & 63;
    out[t] = (X[t] - sred[n]) * sred[16 + n] * gma[ii] + bta[ii];
    __syncthreads();
}

// ---------------------------------------------------------------------------
// mlp lane helpers
// ---------------------------------------------------------------------------
__device__ __forceinline__ void lane_issue(const float* __restrict__ gW, int slot,
                                           float* dst, int lt) {
    const float4* g4 = (const float4*)(gW + (size_t)slot * 4096);
    #pragma unroll
    for (int p = 0; p < 8; p++) {
        int f = lt + p * 128;
        int rr = f >> 4, cc = (f & 15) << 2;
        cp_async16(dst + rr * 68 + cc, g4 + f);
    }
}

__device__ __forceinline__ void dot5(const float* __restrict__ wr,
                                     const float* __restrict__ xb,
                                     float& r0, float& r1, float& r2,
                                     float& r3, float& r4) {
    float a0x=0.f,a0y=0.f,a1x=0.f,a1y=0.f,a2x=0.f,a2y=0.f,a3x=0.f,a3y=0.f,a4x=0.f,a4y=0.f;
    #pragma unroll
    for (int j = 0; j < D; j += 4) {
        float4 w  = *(const float4*)(wr + j);
        float4 c0 = *(const float4*)(xb + j);
        float4 c1 = *(const float4*)(xb + D + j);
        float4 c2 = *(const float4*)(xb + 2 * D + j);
        float4 c3 = *(const float4*)(xb + 3 * D + j);
        float4 c4 = *(const float4*)(xb + 4 * D + j);
        a0x = fmaf(w.x, c0.x, fmaf(w.z, c0.z, a0x));
        a0y = fmaf(w.y, c0.y, fmaf(w.w, c0.w, a0y));
        a1x = fmaf(w.x, c1.x, fmaf(w.z, c1.z, a1x));
        a1y = fmaf(w.y, c1.y, fmaf(w.w, c1.w, a1y));
        a2x = fmaf(w.x, c2.x, fmaf(w.z, c2.z, a2x));
        a2y = fmaf(w.y, c2.y, fmaf(w.w, c2.w, a2y));
        a3x = fmaf(w.x, c3.x, fmaf(w.z, c3.z, a3x));
        a3y = fmaf(w.y, c3.y, fmaf(w.w, c3.w, a3y));
        a4x = fmaf(w.x, c4.x, fmaf(w.z, c4.z, a4x));
        a4y = fmaf(w.y, c4.y, fmaf(w.w, c4.w, a4y));
    }
    r0 = a0x + a0y; r1 = a1x + a1y; r2 = a2x + a2y; r3 = a3x + a3y; r4 = a4x + a4y;
}

// ---------------------------------------------------------------------------
// Fused kernel: block 0 = iter, blocks 1..147 = mlp (5 lanes x 128 threads).
// 148 blocks <= 152 SMs -> all co-resident.
// ---------------------------------------------------------------------------
#define SMEM_BYTES 219264

__global__ void __launch_bounds__(640, 1)
fused_kernel(const float* __restrict__ cc0,
             const float* __restrict__ Wk, const float* __restrict__ bk,
             const float* __restrict__ Wq, const float* __restrict__ bq,
             const float* __restrict__ Wv, const float* __restrict__ bv,
             const float* __restrict__ cc_g, const float* __restrict__ cc_b,
             const float* __restrict__ W_ih, const float* __restrict__ W_hh,
             const float* __restrict__ b_ih, const float* __restrict__ b_hh,
             const float* __restrict__ ln_g, const float* __restrict__ ln_b,
             const float* __restrict__ W1, const float* __restrict__ b1,
             const float* __restrict__ W2, const float* __restrict__ b2,
             const float* __restrict__ Wa, const float* __restrict__ ba,
             const float* __restrict__ Wb, const float* __restrict__ bb,
             float* __restrict__ out) {
    extern __shared__ float sm[];
    const int t = threadIdx.x;

    if (blockIdx.x == 0) {
        // ================= iter role =================
        float* swq  = sm;
        float* swih = sm + 4352;
        float* swhh = sm + 17408;
        float* sw1  = sm + 30464;
        float* sw2  = sm + 39168;
        float* scc  = sm + 47616;
        float* sk   = sm + 48256;
        float* sv   = sm + 48896;
        float* sq   = sm + 49536;
        float* sxu  = sm + 50176;
        float* sgi  = sm + 50816;
        float* sgh  = sm + 52736;
        float* sattn= sm + 54656;
        float* sred = sm + 54784;

        const int n  = t >> 6;
        const int ii = t & 63;

        stage_async<64,  64 >(Wq,   swq,  t);
        stage_async<192, 64 >(W_ih, swih, t);
        stage_async<192, 64 >(W_hh, swhh, t);
        stage_async<128, 64 >(W1,   sw1,  t);
        stage_async<64,  128>(W2,   sw2,  t);
        asm volatile("cp.async.commit_group;");

        scc[t] = cc0[t];

        {   // k, v directly from gmem (overlaps weight stream)
            const float4* ccr = (const float4*)(cc0 + n * 64);
            const float4* wkr = (const float4*)(Wk  + ii * 64);
            const float4* wvr = (const float4*)(Wv  + ii * 64);
            float kx = 0.f, ky = 0.f, vx = 0.f, vy = 0.f;
            #pragma unroll
            for (int j = 0; j < 16; j++) {
                float4 c4 = ccr[j];
                float4 k4 = wkr[j];
                float4 v4 = wvr[j];
                kx = fmaf(c4.x, k4.x, fmaf(c4.z, k4.z, kx));
                ky = fmaf(c4.y, k4.y, fmaf(c4.w, k4.w, ky));
                vx = fmaf(c4.x, v4.x, fmaf(c4.z, v4.z, vx));
                vy = fmaf(c4.y, v4.y, fmaf(c4.w, v4.w, vy));
            }
            sk[t] = kx + ky + bk[ii];
            sv[t] = vx + vy + bv[ii];
        }
        asm volatile("cp.async.wait_group 0;" ::: "memory");
        __syncthreads();

        for (int it = 0; it < 3; it++) {
            lnw(scc, cc_g, cc_b, sxu, sred, t);
            // q-mm and gh-mm concurrently (disjoint threads / smem)
            if (t < 128)       mmr<64, 64, 0>(sxu, swq, bq, sq, t);
            else if (t < 512)  mmr<192, 64, 0>(scc, swhh, b_hh, sgh, t - 128);
            __syncthreads();

            if (t < 100) {   // attn logits
                int an = t / 10, am = t % 10;
                const float* kr = sk + an * D;
                const float* qr = sq + am * D;
                float ax = 0.f, ay = 0.f, az = 0.f, aw = 0.f;
                #pragma unroll
                for (int j = 0; j < D; j += 4) {
                    float4 kv = *(const float4*)(kr + j);
                    float4 qv = *(const float4*)(qr + j);
                    ax = fmaf(kv.x, qv.x, ax);
                    ay = fmaf(kv.y, qv.y, ay);
                    az = fmaf(kv.z, qv.z, az);
                    aw = fmaf(kv.w, qv.w, aw);
                }
                sattn[an * 10 + am] = ((ax + ay) + (az + aw)) * 0.125f;
            }
            __syncthreads();
            if (t < 10) {   // softmax over axis 0 (column m = t), +EPS
                float mx = -1e30f;
                #pragma unroll
                for (int a = 0; a < 10; a++) mx = fmaxf(mx, sattn[a * 10 + t]);
                float ss = 0.f;
                #pragma unroll
                for (int a = 0; a < 10; a++) {
                    float e = __expf(sattn[a * 10 + t] - mx);
                    sattn[a * 10 + t] = e;
                    ss += e;
                }
                float inv = 1.f / ss;
                #pragma unroll
                for (int a = 0; a < 10; a++)
                    sattn[a * 10 + t] = sattn[a * 10 + t] * inv + 1e-8f;
            }
            __syncthreads();
            {   // updates = rownorm(attn) @ v   (row-sum folded in)
                float u = 0.f, ss = 0.f;
                #pragma unroll
                for (int m = 0; m < 10; m++) {
                    float a = sattn[n * 10 + m];
                    ss += a;
                    u = fmaf(a, sv[m * D + ii], u);
                }
                sxu[t] = u / ss;
            }
            __syncthreads();

            mmr<192, 64, 0>(sxu, swih, b_ih, sgi, t);
            __syncthreads();
            {   // GRU
                float ir  = sgi[n * 192 + ii];
                float iz  = sgi[n * 192 + 64 + ii];
                float in_ = sgi[n * 192 + 128 + ii];
                float hr  = sgh[n * 192 + ii];
                float hz  = sgh[n * 192 + 64 + ii];
                float hn  = sgh[n * 192 + 128 + ii];
                float r  = fast_sigmoid(ir + hr);
                float z  = fast_sigmoid(iz + hz);
                float nn = fast_tanh(in_ + r * hn);
                scc[t] = (1.f - z) * nn + z * scc[t];
            }
            __syncthreads();

            lnw(scc, ln_g, ln_b, sxu, sred, t);
            mmr2<128, 64, 1>(sxu, sw1, b1, sgi, t);   // 640 threads
            __syncthreads();
            mmr2<64, 128, 0>(sgi, sw2, b2, sgh, t);   // 320 threads
            __syncthreads();
            scc[t] += sgh[t];
            __syncthreads();
        }

        g_cc[t] = scc[t];
        __threadfence();
        __syncthreads();
        if (t == 0) atomicExch(&g_flag, 1);
        return;
    }

    // ================= mlp role =================
    const int cb = blockIdx.x - 1;
    const int q  = NS / NCB;
    const int r  = NS % NCB;
    const int s0    = cb * q + (cb < r ? cb : r);
    const int count = q + (cb < r ? 1 : 0);

    const int lane = t >> 7;        // 0..4
    const int lt   = t & 127;
    const int i    = lt & 63;
    const int g    = lt >> 6;

    const int q2 = count / 5, r2 = count % 5;
    const int ls0    = s0 + lane * q2 + (lane < r2 ? lane : r2);
    const int lcount = q2 + (lane < r2 ? 1 : 0);

    // 1. L2 prefetch of the whole block range (runs under iter)
    {
        const int nlines = count * 256;
        for (int idx = t; idx < nlines; idx += 640) {
            int slot = s0 + (idx >> 8);
            int line = idx & 255;
            const float* p;
            if (line < 128) p = Wa + (size_t)slot * 4096 + line * 32;
            else            p = Wb + (size_t)slot * 4096 + (line - 128) * 32;
            asm volatile("prefetch.global.L2 [%0];" :: "l"(p));
        }
    }

    // 2. first slot: Wa group, then Wb group (separate commits)
    float* Wab = sm + lane * 8704;
    if (lcount > 0) lane_issue(Wa, ls0, Wab, lt);
    asm volatile("cp.async.commit_group;");
    if (lcount > 0) lane_issue(Wb, ls0, Wab + 4352, lt);
    asm volatile("cp.async.commit_group;");

    // 3. wait for iter's g_cc
    if (t == 0) {
        while (atomicAdd(&g_flag, 0) == 0) { __nanosleep(256); }
    }
    __syncthreads();
    __threadfence();

    // 4. stage scc
    float* scc = sm + 43520;
    #pragma unroll
    for (int p = t; p < 160; p += 640)
        ((float4*)scc)[p] = __ldcg(((const float4*)g_cc) + p);
    __syncthreads();

    float* shl = sm + 44160 + lane * 640;
    float* smx = sm + 47360 + lane * 128;

    // pipeline invariant at loop top: outstanding groups = {Wa(s), Wb(s)}
    for (int k2 = 0; k2 < lcount; k2++) {
        const int s = ls0 + k2;
        // Wa(s) ready; Wb(s) may still be in flight
        asm volatile("cp.async.wait_group 1;" ::: "memory");
        asm volatile("bar.sync %0, 128;" :: "r"(lane + 1) : "memory");

        float bav = __ldg(ba + (s << 6) + i);
        float bbv = __ldg(bb + (s << 6) + i);

        // stage 1: h[nn][i] = relu(Wa[i,:].cc[nn,:] + ba[i]) for 5 nn
        {
            float r0, r1, r2v, r3, r4;
            dot5(Wab + i * 68, scc + g * 5 * D, r0, r1, r2v, r3, r4);
            int n0 = g * 5;
            shl[(n0 + 0) * D + i] = fmaxf(r0 + bav, 0.f);
            shl[(n0 + 1) * D + i] = fmaxf(r1 + bav, 0.f);
            shl[(n0 + 2) * D + i] = fmaxf(r2v + bav, 0.f);
            shl[(n0 + 3) * D + i] = fmaxf(r3 + bav, 0.f);
            shl[(n0 + 4) * D + i] = fmaxf(r4 + bav, 0.f);
        }
        asm volatile("bar.sync %0, 128;" :: "r"(lane + 1) : "memory");

        // Wa buffer free: issue Wa(s+1), then wait for Wb(s)
        if (k2 + 1 < lcount) {
            lane_issue(Wa, s + 1, Wab, lt);
            asm volatile("cp.async.commit_group;");
            asm volatile("cp.async.wait_group 1;" ::: "memory");
        } else {
            asm volatile("cp.async.wait_group 0;" ::: "memory");
        }
        asm volatile("bar.sync %0, 128;" :: "r"(lane + 1) : "memory");

        // stage 2: out[nn][i] = Wb[i,:].h[nn,:] + bb[i], max over nn
        {
            float r0, r1, r2v, r3, r4;
            dot5(Wab + 4352 + i * 68, shl + g * 5 * D, r0, r1, r2v, r3, r4);
            float m0 = fmaxf(r0, r1);
            float m1 = fmaxf(r2v, r3);
            smx[lt] = fmaxf(fmaxf(m0, m1), r4) + bbv;
        }
        asm volatile("bar.sync %0, 128;" :: "r"(lane + 1) : "memory");
        if (g == 0) out[(s << 6) + i] = fmaxf(smx[i], smx[64 + i]);

        // Wb buffer free: issue Wb(s+1)
        if (k2 + 1 < lcount) {
            lane_issue(Wb, s + 1, Wab + 4352, lt);
            asm volatile("cp.async.commit_group;");
        }
    }
}

__global__ void init_kernel() { g_flag = 0; }

// ---------------------------------------------------------------------------
extern "C" void kernel_launch(void* const* d_in, const int* in_sizes, int n_in,
                              void* d_out, int out_size) {
    const float* cc0  = (const float*)d_in[0];
    const float* Wk   = (const float*)d_in[1];
    const float* bk   = (const float*)d_in[2];
    const float* Wq   = (const float*)d_in[3];
    const float* bq   = (const float*)d_in[4];
    const float* Wv   = (const float*)d_in[5];
    const float* bv   = (const float*)d_in[6];
    const float* cc_g = (const float*)d_in[7];
    const float* cc_b = (const float*)d_in[8];
    const float* W_ih = (const float*)d_in[9];
    const float* W_hh = (const float*)d_in[10];
    const float* b_ih = (const float*)d_in[11];
    const float* b_hh = (const float*)d_in[12];
    const float* ln_g = (const float*)d_in[13];
    const float* ln_b = (const float*)d_in[14];
    const float* W1   = (const float*)d_in[15];
    const float* b1   = (const float*)d_in[16];
    const float* W2   = (const float*)d_in[17];
    const float* b2   = (const float*)d_in[18];
    const float* Wa   = (const float*)d_in[19];
    const float* ba   = (const float*)d_in[20];
    const float* Wb   = (const float*)d_in[21];
    const float* bb   = (const float*)d_in[22];
    float* out = (float*)d_out;

    cudaFuncSetAttribute(fused_kernel,
                         cudaFuncAttributeMaxDynamicSharedMemorySize,
                         SMEM_BYTES);

    init_kernel<<<1, 1>>>();
    fused_kernel<<<1 + NCB, 640, SMEM_BYTES>>>(
        cc0, Wk, bk, Wq, bq, Wv, bv, cc_g, cc_b,
        W_ih, W_hh, b_ih, b_hh, ln_g, ln_b, W1, b1, W2, b2,
        Wa, ba, Wb, bb, out);
}